// round 8
// baseline (speedup 1.0000x reference)
#include <cuda_runtime.h>
#include <cstdint>

#define DIM    1024
#define KC     32
#define MROWS  32
#define TPB    64
#define KCH    32
#define NCH    (DIM / KCH)       // 32 chunks
#define PITCHW 20                // 32-bit words per row (16 data + 4 pad)
#define XH_OFF 0
#define XL_OFF (MROWS * PITCHW)          // 640
#define CH_OFF (2 * MROWS * PITCHW)      // 1280
#define CL_OFF (CH_OFF + KC * PITCHW)    // 1920
#define STAGE_W (CL_OFF + KC * PITCHW)   // 2560 words = 10240 B

// split fp32 pair into bf16x2 hi + bf16x2 lo (RN both stages); low half = first arg
static __device__ __forceinline__ void split2(float x0, float x1,
                                              uint32_t& hi2, uint32_t& lo2) {
    asm("cvt.rn.bf16x2.f32 %0, %1, %2;" : "=r"(hi2) : "f"(x1), "f"(x0));
    float h0 = __uint_as_float(hi2 << 16);
    float h1 = __uint_as_float(hi2 & 0xFFFF0000u);
    float l0 = x0 - h0, l1 = x1 - h1;
    asm("cvt.rn.bf16x2.f32 %0, %1, %2;" : "=r"(lo2) : "f"(l1), "f"(l0));
}

static __device__ __forceinline__ void mma_bf16(float* c, const uint32_t* a,
                                                uint32_t b0, uint32_t b1) {
    asm volatile(
        "mma.sync.aligned.m16n8k16.row.col.f32.bf16.bf16.f32 "
        "{%0,%1,%2,%3}, {%4,%5,%6,%7}, {%8,%9}, {%0,%1,%2,%3};"
        : "+f"(c[0]), "+f"(c[1]), "+f"(c[2]), "+f"(c[3])
        : "r"(a[0]), "r"(a[1]), "r"(a[2]), "r"(a[3]), "r"(b0), "r"(b1));
}

__global__ __launch_bounds__(TPB, 10)
void nkm_mma(const float* __restrict__ X, const float* __restrict__ C,
             float* __restrict__ out, int N) {
    __shared__ uint32_t sbuf[2][STAGE_W];   // 20480 B double-buffered stage
    __shared__ float sSq[KC];

    const int tid  = threadIdx.x;
    const int w    = tid >> 5;        // 0..1
    const int lane = tid & 31;
    const int g    = lane >> 2;       // fragment row group 0..7
    const int ql   = lane & 3;        // fragment k/col phase 0..3
    const int blockBase = blockIdx.x * MROWS;

    const float4* __restrict__ X4 = reinterpret_cast<const float4*>(X);
    const float4* __restrict__ C4 = reinterpret_cast<const float4*>(C);

    // ---- loader constants ----
    // X tile: 32 rows x 8 float4; thread loads rows (tid>>3)+8j (j=0..3), col4 = tid&7
    int xg[4], cg[4];
    uint32_t stsXC[4];
#pragma unroll
    for (int j = 0; j < 4; j++) {
        int row = (tid >> 3) + 8 * j;
        int gr  = blockBase + row;
        if (gr >= N) gr = N - 1;            // clamp; outputs guarded
        xg[j]    = gr * (DIM / 4) + (tid & 7);
        cg[j]    = row * (DIM / 4) + (tid & 7);
        stsXC[j] = (uint32_t)(row * PITCHW + (tid & 7) * 2);
    }

    float acc[4][4];                 // [ntile][frag]: rows {g,g+8} x classes {8nt+2ql,+1}
#pragma unroll
    for (int nt = 0; nt < 4; nt++)
#pragma unroll
        for (int i = 0; i < 4; i++) acc[nt][i] = 0.0f;

    float sq[4] = {0.f, 0.f, 0.f, 0.f};   // ||mu||^2 partials, rows (tid>>3)+8j

    // fragment LDS base (word index): warp w owns rows 16w..16w+15
    const int abase = (16 * w + g) * PITCHW + ql;

    // ---- prologue: chunk 0 -> buf 0 ----
    {
        uint32_t* b = sbuf[0];
#pragma unroll
        for (int j = 0; j < 4; j++) {
            float4 v = X4[xg[j]];
            uint32_t h0, l0, h1, l1;
            split2(v.x, v.y, h0, l0);
            split2(v.z, v.w, h1, l1);
            *reinterpret_cast<uint2*>(b + XH_OFF + stsXC[j]) = make_uint2(h0, h1);
            *reinterpret_cast<uint2*>(b + XL_OFF + stsXC[j]) = make_uint2(l0, l1);
        }
#pragma unroll
        for (int j = 0; j < 4; j++) {
            float4 v = C4[cg[j]];
            sq[j] += v.x * v.x + v.y * v.y + v.z * v.z + v.w * v.w;
            uint32_t h0, l0, h1, l1;
            split2(v.x, v.y, h0, l0);
            split2(v.z, v.w, h1, l1);
            *reinterpret_cast<uint2*>(b + CH_OFF + stsXC[j]) = make_uint2(h0, h1);
            *reinterpret_cast<uint2*>(b + CL_OFF + stsXC[j]) = make_uint2(l0, l1);
        }
    }
    __syncthreads();

    // ---- main loop ----
#pragma unroll 1
    for (int kt = 0; kt < NCH; kt++) {
        float4 xr[4], cr[4];
        const bool more = (kt + 1 < NCH);
        if (more) {
            const int kc4 = (kt + 1) * 8;
#pragma unroll
            for (int j = 0; j < 4; j++) xr[j] = X4[xg[j] + kc4];
#pragma unroll
            for (int j = 0; j < 4; j++) cr[j] = C4[cg[j] + kc4];
        }

        // compute chunk kt from sbuf[kt&1]
        const uint32_t* bp = sbuf[kt & 1];
#pragma unroll
        for (int ks = 0; ks < 2; ks++) {
            const int ko = 8 * ks;
            uint32_t ah[4], al[4];
            const int a0 = XH_OFF + abase + ko;
            ah[0] = bp[a0];
            ah[1] = bp[a0 + 8 * PITCHW];
            ah[2] = bp[a0 + 4];
            ah[3] = bp[a0 + 8 * PITCHW + 4];
            const int a0l = a0 + (XL_OFF - XH_OFF);
            al[0] = bp[a0l];
            al[1] = bp[a0l + 8 * PITCHW];
            al[2] = bp[a0l + 4];
            al[3] = bp[a0l + 8 * PITCHW + 4];
#pragma unroll
            for (int nt = 0; nt < 4; nt++) {
                const int b0i = CH_OFF + (8 * nt + g) * PITCHW + ql + ko;
                uint32_t bh0 = bp[b0i], bh1 = bp[b0i + 4];
                uint32_t bl0 = bp[b0i + (CL_OFF - CH_OFF)];
                uint32_t bl1 = bp[b0i + (CL_OFF - CH_OFF) + 4];
                mma_bf16(acc[nt], ah, bh0, bh1);   // hi*hi
                mma_bf16(acc[nt], ah, bl0, bl1);   // hi*lo
                mma_bf16(acc[nt], al, bh0, bh1);   // lo*hi
            }
        }

        if (more) {
            uint32_t* b = sbuf[(kt + 1) & 1];
#pragma unroll
            for (int j = 0; j < 4; j++) {
                uint32_t h0, l0, h1, l1;
                split2(xr[j].x, xr[j].y, h0, l0);
                split2(xr[j].z, xr[j].w, h1, l1);
                *reinterpret_cast<uint2*>(b + XH_OFF + stsXC[j]) = make_uint2(h0, h1);
                *reinterpret_cast<uint2*>(b + XL_OFF + stsXC[j]) = make_uint2(l0, l1);
            }
#pragma unroll
            for (int j = 0; j < 4; j++) {
                sq[j] += cr[j].x * cr[j].x + cr[j].y * cr[j].y
                       + cr[j].z * cr[j].z + cr[j].w * cr[j].w;
                uint32_t h0, l0, h1, l1;
                split2(cr[j].x, cr[j].y, h0, l0);
                split2(cr[j].z, cr[j].w, h1, l1);
                *reinterpret_cast<uint2*>(b + CH_OFF + stsXC[j]) = make_uint2(h0, h1);
                *reinterpret_cast<uint2*>(b + CL_OFF + stsXC[j]) = make_uint2(l0, l1);
            }
        }
        __syncthreads();
    }

    // ---- ||mu||^2 reduce: 8 threads (col pieces) per class row ----
#pragma unroll
    for (int j = 0; j < 4; j++) {
        sq[j] += __shfl_down_sync(0xffffffffu, sq[j], 4, 8);
        sq[j] += __shfl_down_sync(0xffffffffu, sq[j], 2, 8);
        sq[j] += __shfl_down_sync(0xffffffffu, sq[j], 1, 8);
    }
    if ((tid & 7) == 0) {
#pragma unroll
        for (int j = 0; j < 4; j++) sSq[(tid >> 3) + 8 * j] = sq[j];
    }
    __syncthreads();

    // ---- epilogue: s = 2*dot - sq ; top2 per row; merge across quad ----
    const float NEG_INF = -__int_as_float(0x7f800000);
    float m1[2] = {NEG_INF, NEG_INF};
    float m2[2] = {NEG_INF, NEG_INF};
#pragma unroll
    for (int nt = 0; nt < 4; nt++) {
        const int c0 = 8 * nt + ql * 2;
        const float q0 = sSq[c0], q1 = sSq[c0 + 1];
        float s;
        s = 2.0f * acc[nt][0] - q0;
        if (s > m1[0]) { m2[0] = m1[0]; m1[0] = s; } else if (s > m2[0]) m2[0] = s;
        s = 2.0f * acc[nt][1] - q1;
        if (s > m1[0]) { m2[0] = m1[0]; m1[0] = s; } else if (s > m2[0]) m2[0] = s;
        s = 2.0f * acc[nt][2] - q0;
        if (s > m1[1]) { m2[1] = m1[1]; m1[1] = s; } else if (s > m2[1]) m2[1] = s;
        s = 2.0f * acc[nt][3] - q1;
        if (s > m1[1]) { m2[1] = m1[1]; m1[1] = s; } else if (s > m2[1]) m2[1] = s;
    }
#pragma unroll
    for (int delta = 1; delta <= 2; delta <<= 1) {
#pragma unroll
        for (int r = 0; r < 2; r++) {
            float om1 = __shfl_xor_sync(0xffffffffu, m1[r], delta);
            float om2 = __shfl_xor_sync(0xffffffffu, m2[r], delta);
            float nm1 = fmaxf(m1[r], om1);
            float nm2 = fmaxf(fminf(m1[r], om1), fmaxf(m2[r], om2));
            m1[r] = nm1;
            m2[r] = nm2;
        }
    }
    if (ql == 0) {
        int r0 = blockBase + 16 * w + g;
        if (r0 < N)     out[r0]     = m1[0] - m2[0];
        if (r0 + 8 < N) out[r0 + 8] = m1[1] - m2[1];
    }
}

extern "C" void kernel_launch(void* const* d_in, const int* in_sizes, int n_in,
                              void* d_out, int out_size) {
    const float* X = (const float*)d_in[0];   // [N, 1024]
    const float* C = (const float*)d_in[1];   // [32, 1024]
    float* out = (float*)d_out;               // [N]
    int N = in_sizes[0] / DIM;
    int nb = (N + MROWS - 1) / MROWS;

    // allow max shared-memory carveout so 10 CTAs/SM fit
    cudaFuncSetAttribute(nkm_mma, cudaFuncAttributePreferredSharedMemoryCarveout, 100);
    nkm_mma<<<nb, TPB>>>(X, C, out, N);
}

// round 9
// speedup vs baseline: 1.6578x; 1.6578x over previous
#include <cuda_runtime.h>
#include <cstdint>

#define DIM    1024
#define KC     32
#define MROWS  128
#define TPB    256
#define KCH    32
#define NCH    (DIM / KCH)        // 32 chunks
// X stage: fp32, row pitch 40 words (160B) -> conflict-free LDS.64 fragments
#define PXB    160
#define XST_B  (MROWS * PXB)              // 20480 B
// C stage: bf16x2 words, row pitch 20 words (80B) (same as proven R6 layout)
#define PCB    80
#define CHI_REL XST_B                      // 20480
#define CLO_REL (XST_B + KC * PCB)         // 23040
#define STAGE_B (XST_B + 2 * KC * PCB)     // 25600 B
#define SSQ_REL (2 * STAGE_B)              // 51200
#define SMEM_B  (SSQ_REL + KC * 4)         // 51328 B

// ---- device scratch (legal: __device__ globals) ----
__device__ __align__(16) unsigned short g_Chi[KC * DIM];
__device__ __align__(16) unsigned short g_Clo[KC * DIM];
__device__ float g_sSq[KC];

static __device__ __forceinline__ uint32_t s2u(const void* p) {
    uint32_t a;
    asm("{ .reg .u64 t; cvta.to.shared.u64 t, %1; cvt.u32.u64 %0, t; }" : "=r"(a) : "l"(p));
    return a;
}
static __device__ __forceinline__ uint64_t g2u(const void* p) {
    uint64_t a;
    asm("cvta.to.global.u64 %0, %1;" : "=l"(a) : "l"(p));
    return a;
}

// split fp32 pair into bf16x2 hi + bf16x2 lo (RN both stages); low half = first arg
static __device__ __forceinline__ void split2(float x0, float x1,
                                              uint32_t& hi2, uint32_t& lo2) {
    asm("cvt.rn.bf16x2.f32 %0, %1, %2;" : "=r"(hi2) : "f"(x1), "f"(x0));
    float h0 = __uint_as_float(hi2 << 16);
    float h1 = __uint_as_float(hi2 & 0xFFFF0000u);
    float l0 = x0 - h0, l1 = x1 - h1;
    asm("cvt.rn.bf16x2.f32 %0, %1, %2;" : "=r"(lo2) : "f"(l1), "f"(l0));
}

static __device__ __forceinline__ void mma_bf16(float* c, const uint32_t* a,
                                                uint32_t b0, uint32_t b1) {
    asm volatile(
        "mma.sync.aligned.m16n8k16.row.col.f32.bf16.bf16.f32 "
        "{%0,%1,%2,%3}, {%4,%5,%6,%7}, {%8,%9}, {%0,%1,%2,%3};"
        : "+f"(c[0]), "+f"(c[1]), "+f"(c[2]), "+f"(c[3])
        : "r"(a[0]), "r"(a[1]), "r"(a[2]), "r"(a[3]), "r"(b0), "r"(b1));
}

#define CPA16(dst, src) asm volatile("cp.async.cg.shared.global [%0], [%1], 16;" :: "r"(dst), "l"(src) : "memory")
#define CPA8(dst, src)  asm volatile("cp.async.ca.shared.global [%0], [%1], 8;"  :: "r"(dst), "l"(src) : "memory")
#define CPA_COMMIT()    asm volatile("cp.async.commit_group;" ::: "memory")
#define CPA_WAIT1()     asm volatile("cp.async.wait_group 1;" ::: "memory")
#define CPA_WAIT0()     asm volatile("cp.async.wait_group 0;" ::: "memory")
#define LDS64F(vx, vy, a) asm volatile("ld.shared.v2.f32 {%0,%1},[%2];" : "=f"(vx), "=f"(vy) : "r"(a))
#define LDS32U(v, a)      asm volatile("ld.shared.b32 %0,[%1];" : "=r"(v) : "r"(a))

// ---- kernel 1: pre-split C into bf16 hi/lo + compute ||mu||^2 ----
__global__ void conv_c(const float* __restrict__ C) {
    __shared__ float wsum[4];
    const int row = blockIdx.x;
    const int t = threadIdx.x;
    const float4* __restrict__ C4 = reinterpret_cast<const float4*>(C);
    float sq = 0.0f;
#pragma unroll
    for (int i = 0; i < 2; i++) {
        int f4 = t + 128 * i;
        float4 v = C4[row * 256 + f4];
        sq += v.x * v.x + v.y * v.y + v.z * v.z + v.w * v.w;
        uint32_t h0, l0, h1, l1;
        split2(v.x, v.y, h0, l0);
        split2(v.z, v.w, h1, l1);
        reinterpret_cast<uint2*>(g_Chi)[row * 256 + f4] = make_uint2(h0, h1);
        reinterpret_cast<uint2*>(g_Clo)[row * 256 + f4] = make_uint2(l0, l1);
    }
#pragma unroll
    for (int d = 16; d; d >>= 1) sq += __shfl_down_sync(0xffffffffu, sq, d);
    if ((t & 31) == 0) wsum[t >> 5] = sq;
    __syncthreads();
    if (t == 0) g_sSq[row] = wsum[0] + wsum[1] + wsum[2] + wsum[3];
}

// ---- kernel 2: main GEMM + top2 ----
__global__ __launch_bounds__(TPB, 3)
void nkm_mma(const float* __restrict__ X, float* __restrict__ out, int N) {
    extern __shared__ char smem[];
    const uint32_t sb = s2u(smem);
    float* sSqS = reinterpret_cast<float*>(smem + SSQ_REL);

    const int tid  = threadIdx.x;
    const int w    = tid >> 5;        // 0..7, warp owns rows 16w..16w+15
    const int lane = tid & 31;
    const int g    = lane >> 2;
    const int ql   = lane & 3;
    const int blockBase = blockIdx.x * MROWS;

    if (tid < KC) sSqS[tid] = g_sSq[tid];

    // ---- cp.async source/dest maps ----
    // X: 4 transfers of 16B each; transfer i: idx=tid+256i -> row idx>>3, f4 idx&7
    const uint64_t Xg = g2u(X);
    uint64_t xsrc[4];
    uint32_t xdst[4];
#pragma unroll
    for (int i = 0; i < 4; i++) {
        int idx = tid + 256 * i;
        int r = idx >> 3, f = idx & 7;
        int gr = blockBase + r;
        if (gr >= N) gr = N - 1;      // clamp; outputs guarded
        xsrc[i] = Xg + ((uint64_t)gr * DIM + 4 * (uint64_t)f) * 4ull;
        xdst[i] = (uint32_t)(PXB * r + 16 * f);
    }
    // C hi/lo: 1 transfer of 8B each; row tid>>3, seg tid&7 (4 bf16)
    const int cr = tid >> 3, cs = tid & 7;
    const uint64_t hisrc = g2u(g_Chi) + ((uint64_t)cr * DIM + 4 * (uint64_t)cs) * 2ull;
    const uint64_t losrc = g2u(g_Clo) + ((uint64_t)cr * DIM + 4 * (uint64_t)cs) * 2ull;
    const uint32_t cdst = (uint32_t)(PCB * cr + 8 * cs);

    float acc[4][4];
#pragma unroll
    for (int nt = 0; nt < 4; nt++)
#pragma unroll
        for (int i = 0; i < 4; i++) acc[nt][i] = 0.0f;

    // ---- stage issue helper (inline) ----
#define ISSUE(ktv)                                                              \
    do {                                                                        \
        uint32_t _bs = sb + (uint32_t)((ktv) & 1) * STAGE_B;                    \
        uint64_t _ko = (uint64_t)(ktv) * (KCH * 4);                             \
        CPA16(_bs + xdst[0], xsrc[0] + _ko);                                    \
        CPA16(_bs + xdst[1], xsrc[1] + _ko);                                    \
        CPA16(_bs + xdst[2], xsrc[2] + _ko);                                    \
        CPA16(_bs + xdst[3], xsrc[3] + _ko);                                    \
        CPA8(_bs + CHI_REL + cdst, hisrc + (uint64_t)(ktv) * (KCH * 2));        \
        CPA8(_bs + CLO_REL + cdst, losrc + (uint64_t)(ktv) * (KCH * 2));        \
        CPA_COMMIT();                                                           \
    } while (0)

    ISSUE(0);
    ISSUE(1);

    const uint32_t aRow = (uint32_t)(PXB * (16 * w + g));   // X row byte offset
#pragma unroll 1
    for (int kt = 0; kt < NCH; kt++) {
        if (kt + 1 < NCH) { CPA_WAIT1(); } else { CPA_WAIT0(); }
        __syncthreads();

        const uint32_t bb = sb + (uint32_t)(kt & 1) * STAGE_B;
#pragma unroll
        for (int s = 0; s < 2; s++) {
            // A fragments: fp32 LDS.64 + in-register split
            const uint32_t aa = bb + aRow + 8 * ql + 64 * s;
            float2 f0, f1, f2, f3;
            LDS64F(f0.x, f0.y, aa);                 // row g,   k 2ql..
            LDS64F(f1.x, f1.y, aa + 8 * PXB);       // row g+8
            LDS64F(f2.x, f2.y, aa + 32);            // row g,   k+8
            LDS64F(f3.x, f3.y, aa + 8 * PXB + 32);  // row g+8, k+8
            uint32_t ah[4], al[4];
            split2(f0.x, f0.y, ah[0], al[0]);
            split2(f1.x, f1.y, ah[1], al[1]);
            split2(f2.x, f2.y, ah[2], al[2]);
            split2(f3.x, f3.y, ah[3], al[3]);

            const uint32_t bbase = bb + CHI_REL + 4 * ql + 32 * s;
#pragma unroll
            for (int nt = 0; nt < 4; nt++) {
                const uint32_t bba = bbase + (uint32_t)(PCB * (8 * nt + g));
                uint32_t bh0, bh1, bl0, bl1;
                LDS32U(bh0, bba);
                LDS32U(bh1, bba + 16);
                LDS32U(bl0, bba + (CLO_REL - CHI_REL));
                LDS32U(bl1, bba + (CLO_REL - CHI_REL) + 16);
                mma_bf16(acc[nt], ah, bh0, bh1);   // hi*hi
                mma_bf16(acc[nt], ah, bl0, bl1);   // hi*lo
                mma_bf16(acc[nt], al, bh0, bh1);   // lo*hi
            }
        }
        __syncthreads();
        if (kt + 2 < NCH) ISSUE(kt + 2);
    }

    // ---- epilogue: s = 2*dot - sq ; top2 per row; merge across quad ----
    const float NEG_INF = -__int_as_float(0x7f800000);
    float m1[2] = {NEG_INF, NEG_INF};
    float m2[2] = {NEG_INF, NEG_INF};
#pragma unroll
    for (int nt = 0; nt < 4; nt++) {
        const int c0 = 8 * nt + ql * 2;
        const float q0 = sSqS[c0], q1 = sSqS[c0 + 1];
        float s;
        s = 2.0f * acc[nt][0] - q0;
        if (s > m1[0]) { m2[0] = m1[0]; m1[0] = s; } else if (s > m2[0]) m2[0] = s;
        s = 2.0f * acc[nt][1] - q1;
        if (s > m1[0]) { m2[0] = m1[0]; m1[0] = s; } else if (s > m2[0]) m2[0] = s;
        s = 2.0f * acc[nt][2] - q0;
        if (s > m1[1]) { m2[1] = m1[1]; m1[1] = s; } else if (s > m2[1]) m2[1] = s;
        s = 2.0f * acc[nt][3] - q1;
        if (s > m1[1]) { m2[1] = m1[1]; m1[1] = s; } else if (s > m2[1]) m2[1] = s;
    }
#pragma unroll
    for (int delta = 1; delta <= 2; delta <<= 1) {
#pragma unroll
        for (int r = 0; r < 2; r++) {
            float om1 = __shfl_xor_sync(0xffffffffu, m1[r], delta);
            float om2 = __shfl_xor_sync(0xffffffffu, m2[r], delta);
            float nm1 = fmaxf(m1[r], om1);
            float nm2 = fmaxf(fminf(m1[r], om1), fmaxf(m2[r], om2));
            m1[r] = nm1;
            m2[r] = nm2;
        }
    }
    if (ql == 0) {
        int r0 = blockBase + 16 * w + g;
        if (r0 < N)     out[r0]     = m1[0] - m2[0];
        if (r0 + 8 < N) out[r0 + 8] = m1[1] - m2[1];
    }
#undef ISSUE
}

extern "C" void kernel_launch(void* const* d_in, const int* in_sizes, int n_in,
                              void* d_out, int out_size) {
    const float* X = (const float*)d_in[0];   // [N, 1024]
    const float* C = (const float*)d_in[1];   // [32, 1024]
    float* out = (float*)d_out;               // [N]
    int N = in_sizes[0] / DIM;
    int nb = (N + MROWS - 1) / MROWS;

    conv_c<<<KC, 128>>>(C);

    cudaFuncSetAttribute(nkm_mma, cudaFuncAttributeMaxDynamicSharedMemorySize, SMEM_B);
    nkm_mma<<<nb, TPB, SMEM_B>>>(X, out, N);
}

// round 10
// speedup vs baseline: 1.7179x; 1.0362x over previous
#include <cuda_runtime.h>
#include <cstdint>

#define DIM    1024
#define KC     32
#define MROWS  128
#define TPB    256
#define KCH    32
#define NCH    (DIM / KCH)        // 32 chunks
// X stage: fp32, row pitch 160B -> conflict-free LDS.64 fragments
#define PXB    160
#define XST_B  (MROWS * PXB)              // 20480 B
#define CP_REL XST_B                      // packed C region within stage
#define CP_B   4096                       // 256 threads * 16B
#define STAGE_B (XST_B + CP_B)            // 24576 B
#define NSTG   3
#define SSQ_REL (NSTG * STAGE_B)          // 73728
#define SMEM_B  (SSQ_REL + KC * 4)        // 73856 B

// ---- device scratch ----
// g_Cp[(kt*8 + nt*2 + s)*32 + lane] = {bh0, bh1, bl0, bl1}
__device__ __align__(16) uint4 g_Cp[NCH * 8 * 32];   // 128 KB
__device__ float g_sSq[KC];

static __device__ __forceinline__ uint32_t s2u(const void* p) {
    uint32_t a;
    asm("{ .reg .u64 t; cvta.to.shared.u64 t, %1; cvt.u32.u64 %0, t; }" : "=r"(a) : "l"(p));
    return a;
}
static __device__ __forceinline__ uint64_t g2u(const void* p) {
    uint64_t a;
    asm("cvta.to.global.u64 %0, %1;" : "=l"(a) : "l"(p));
    return a;
}

// split fp32 pair into bf16x2 hi + bf16x2 lo (RN both stages); low half = first arg
static __device__ __forceinline__ void split2(float x0, float x1,
                                              uint32_t& hi2, uint32_t& lo2) {
    asm("cvt.rn.bf16x2.f32 %0, %1, %2;" : "=r"(hi2) : "f"(x1), "f"(x0));
    float h0 = __uint_as_float(hi2 << 16);
    float h1 = __uint_as_float(hi2 & 0xFFFF0000u);
    float l0 = x0 - h0, l1 = x1 - h1;
    asm("cvt.rn.bf16x2.f32 %0, %1, %2;" : "=r"(lo2) : "f"(l1), "f"(l0));
}

static __device__ __forceinline__ void mma_bf16(float* c, const uint32_t* a,
                                                uint32_t b0, uint32_t b1) {
    asm volatile(
        "mma.sync.aligned.m16n8k16.row.col.f32.bf16.bf16.f32 "
        "{%0,%1,%2,%3}, {%4,%5,%6,%7}, {%8,%9}, {%0,%1,%2,%3};"
        : "+f"(c[0]), "+f"(c[1]), "+f"(c[2]), "+f"(c[3])
        : "r"(a[0]), "r"(a[1]), "r"(a[2]), "r"(a[3]), "r"(b0), "r"(b1));
}

#define CPA16(dst, src) asm volatile("cp.async.cg.shared.global [%0], [%1], 16;" :: "r"(dst), "l"(src) : "memory")
#define CPA_COMMIT()    asm volatile("cp.async.commit_group;" ::: "memory")
#define LDS64F(vx, vy, a) asm volatile("ld.shared.v2.f32 {%0,%1},[%2];" : "=f"(vx), "=f"(vy) : "r"(a))
#define LDS128U(r0, r1, r2, r3, a) \
    asm volatile("ld.shared.v4.b32 {%0,%1,%2,%3},[%4];" \
                 : "=r"(r0), "=r"(r1), "=r"(r2), "=r"(r3) : "r"(a))

// ---- setup: pack C fragments + ||mu||^2 ----
__global__ void pack_c(const float* __restrict__ C) {
    const int kt = blockIdx.x;
    const int t  = threadIdx.x;
    const int l = t & 31, s = (t >> 5) & 1, nt = t >> 6;
    const int g = l >> 2, ql = l & 3;
    const int row = 8 * nt + g;
    const int k0 = 32 * kt + 16 * s + 2 * ql;

    float a0 = C[row * DIM + k0],     a1 = C[row * DIM + k0 + 1];
    float b0 = C[row * DIM + k0 + 8], b1 = C[row * DIM + k0 + 9];
    uint32_t w0, w1, w2, w3;
    split2(a0, a1, w0, w2);
    split2(b0, b1, w1, w3);
    g_Cp[(kt * 8 + nt * 2 + s) * 32 + l] = make_uint4(w0, w1, w2, w3);

    if (kt == 0) {   // block 0 also computes ||mu||^2: 8 threads per row
        const int r = t >> 3, part = t & 7;
        const float4* C4 = reinterpret_cast<const float4*>(C);
        float sq = 0.0f;
#pragma unroll
        for (int i = 0; i < 32; i++) {
            float4 v = C4[r * 256 + part * 32 + i];
            sq += v.x * v.x + v.y * v.y + v.z * v.z + v.w * v.w;
        }
        sq += __shfl_down_sync(0xffffffffu, sq, 4, 8);
        sq += __shfl_down_sync(0xffffffffu, sq, 2, 8);
        sq += __shfl_down_sync(0xffffffffu, sq, 1, 8);
        if (part == 0) g_sSq[r] = sq;
    }
}

// ---- main GEMM + top2 ----
__global__ __launch_bounds__(TPB, 3)
void nkm_mma(const float* __restrict__ X, float* __restrict__ out, int N) {
    extern __shared__ char smem[];
    const uint32_t sb = s2u(smem);
    float* sSqS = reinterpret_cast<float*>(smem + SSQ_REL);

    const int tid  = threadIdx.x;
    const int w    = tid >> 5;        // 0..7, warp owns rows 16w..16w+15
    const int lane = tid & 31;
    const int g    = lane >> 2;
    const int ql   = lane & 3;
    const int blockBase = blockIdx.x * MROWS;

    if (tid < KC) sSqS[tid] = g_sSq[tid];

    // ---- cp.async source/dest maps ----
    const uint64_t Xg = g2u(X);
    uint64_t xsrc[4];
    uint32_t xdst[4];
#pragma unroll
    for (int i = 0; i < 4; i++) {
        int idx = tid + 256 * i;
        int r = idx >> 3, f = idx & 7;
        int gr = blockBase + r;
        if (gr >= N) gr = N - 1;      // clamp; outputs guarded
        xsrc[i] = Xg + ((uint64_t)gr * DIM + 4 * (uint64_t)f) * 4ull;
        xdst[i] = (uint32_t)(PXB * r + 16 * f);
    }
    const uint64_t csrc = g2u(g_Cp) + (uint64_t)tid * 16ull;
    const uint32_t cdst = CP_REL + (uint32_t)tid * 16u;

    float acc[4][4];
#pragma unroll
    for (int nt = 0; nt < 4; nt++)
#pragma unroll
        for (int i = 0; i < 4; i++) acc[nt][i] = 0.0f;

#define ISSUE(ktv, stg)                                                         \
    do {                                                                        \
        uint32_t _bs = sb + (uint32_t)(stg) * STAGE_B;                          \
        uint64_t _ko = (uint64_t)(ktv) * (KCH * 4);                             \
        CPA16(_bs + xdst[0], xsrc[0] + _ko);                                    \
        CPA16(_bs + xdst[1], xsrc[1] + _ko);                                    \
        CPA16(_bs + xdst[2], xsrc[2] + _ko);                                    \
        CPA16(_bs + xdst[3], xsrc[3] + _ko);                                    \
        CPA16(_bs + cdst, csrc + (uint64_t)(ktv) * CP_B);                       \
        CPA_COMMIT();                                                           \
    } while (0)

    ISSUE(0, 0);
    ISSUE(1, 1);

    const uint32_t aRow = (uint32_t)(PXB * (16 * w + g));   // X row byte offset
    const uint32_t bIdx = (uint32_t)(lane * 16);            // packed C lane offset

    int rd = 0;                       // read stage = kt % 3
#pragma unroll 1
    for (int kt = 0; kt < NCH; kt++) {
        if (kt + 1 < NCH) {
            asm volatile("cp.async.wait_group 1;" ::: "memory");
        } else {
            asm volatile("cp.async.wait_group 0;" ::: "memory");
        }
        __syncthreads();              // stage kt visible; stage (kt-1)%3 freed

        if (kt + 2 < NCH) {
            int ib = rd + 2; if (ib >= NSTG) ib -= NSTG;
            ISSUE(kt + 2, ib);
        }

        const uint32_t bb = sb + (uint32_t)rd * STAGE_B;
#pragma unroll
        for (int s = 0; s < 2; s++) {
            // A fragments: fp32 LDS.64 + in-register split
            const uint32_t aa = bb + aRow + 8 * ql + 64 * s;
            float2 f0, f1, f2, f3;
            LDS64F(f0.x, f0.y, aa);                 // row g,   k 2ql..
            LDS64F(f1.x, f1.y, aa + 8 * PXB);       // row g+8
            LDS64F(f2.x, f2.y, aa + 32);            // row g,   k+8
            LDS64F(f3.x, f3.y, aa + 8 * PXB + 32);  // row g+8, k+8
            uint32_t ah[4], al[4];
            split2(f0.x, f0.y, ah[0], al[0]);
            split2(f1.x, f1.y, ah[1], al[1]);
            split2(f2.x, f2.y, ah[2], al[2]);
            split2(f3.x, f3.y, ah[3], al[3]);

#pragma unroll
            for (int nt = 0; nt < 4; nt++) {
                uint32_t bh0, bh1, bl0, bl1;
                LDS128U(bh0, bh1, bl0, bl1,
                        bb + CP_REL + (uint32_t)((nt * 2 + s) * 512) + bIdx);
                mma_bf16(acc[nt], ah, bh0, bh1);   // hi*hi
                mma_bf16(acc[nt], ah, bl0, bl1);   // hi*lo
                mma_bf16(acc[nt], al, bh0, bh1);   // lo*hi
            }
        }
        if (++rd == NSTG) rd = 0;
    }

    // ---- epilogue: s = 2*dot - sq ; top2 per row; merge across quad ----
    const float NEG_INF = -__int_as_float(0x7f800000);
    float m1[2] = {NEG_INF, NEG_INF};
    float m2[2] = {NEG_INF, NEG_INF};
#pragma unroll
    for (int nt = 0; nt < 4; nt++) {
        const int c0 = 8 * nt + ql * 2;
        const float q0 = sSqS[c0], q1 = sSqS[c0 + 1];
        float s;
        s = 2.0f * acc[nt][0] - q0;
        if (s > m1[0]) { m2[0] = m1[0]; m1[0] = s; } else if (s > m2[0]) m2[0] = s;
        s = 2.0f * acc[nt][1] - q1;
        if (s > m1[0]) { m2[0] = m1[0]; m1[0] = s; } else if (s > m2[0]) m2[0] = s;
        s = 2.0f * acc[nt][2] - q0;
        if (s > m1[1]) { m2[1] = m1[1]; m1[1] = s; } else if (s > m2[1]) m2[1] = s;
        s = 2.0f * acc[nt][3] - q1;
        if (s > m1[1]) { m2[1] = m1[1]; m1[1] = s; } else if (s > m2[1]) m2[1] = s;
    }
#pragma unroll
    for (int delta = 1; delta <= 2; delta <<= 1) {
#pragma unroll
        for (int r = 0; r < 2; r++) {
            float om1 = __shfl_xor_sync(0xffffffffu, m1[r], delta);
            float om2 = __shfl_xor_sync(0xffffffffu, m2[r], delta);
            float nm1 = fmaxf(m1[r], om1);
            float nm2 = fmaxf(fminf(m1[r], om1), fmaxf(m2[r], om2));
            m1[r] = nm1;
            m2[r] = nm2;
        }
    }
    if (ql == 0) {
        int r0 = blockBase + 16 * w + g;
        if (r0 < N)     out[r0]     = m1[0] - m2[0];
        if (r0 + 8 < N) out[r0 + 8] = m1[1] - m2[1];
    }
#undef ISSUE
}

extern "C" void kernel_launch(void* const* d_in, const int* in_sizes, int n_in,
                              void* d_out, int out_size) {
    const float* X = (const float*)d_in[0];   // [N, 1024]
    const float* C = (const float*)d_in[1];   // [32, 1024]
    float* out = (float*)d_out;               // [N]
    int N = in_sizes[0] / DIM;
    int nb = (N + MROWS - 1) / MROWS;

    pack_c<<<NCH, TPB>>>(C);

    cudaFuncSetAttribute(nkm_mma, cudaFuncAttributeMaxDynamicSharedMemorySize, SMEM_B);
    nkm_mma<<<nb, TPB, SMEM_B>>>(X, out, N);
}

// round 11
// speedup vs baseline: 1.9518x; 1.1362x over previous
#include <cuda_runtime.h>
#include <cstdint>

#define DIM    1024
#define KC     32
#define MROWS  128
#define TPB    256
#define KCH    32
#define NCH    (DIM / KCH)        // 32 chunks
// X stage: fp32, row pitch 160B -> conflict-free LDS.64 fragments
#define PXB    160
#define XST_B  (MROWS * PXB)              // 20480 B
#define CP_REL XST_B                      // packed C region within stage
#define CP_B   4096                       // 256 threads * 16B
#define STAGE_B (XST_B + CP_B)            // 24576 B
#define NSTG   3
#define SSQ_REL (NSTG * STAGE_B)          // 73728
#define SMEM_B  (SSQ_REL + KC * 4)        // 73856 B

// ---- device scratch ----
// g_Cp[(kt*8 + nt*2 + s)*32 + lane] = {bh0, bh1, bl0, bl1}
__device__ __align__(16) uint4 g_Cp[NCH * 8 * 32];   // 128 KB
__device__ float g_sqPart[NCH * KC];                 // per-chunk ||mu||^2 partials
__device__ unsigned int g_ctr;                       // pack completion counter

static __device__ __forceinline__ uint32_t s2u(const void* p) {
    uint32_t a;
    asm("{ .reg .u64 t; cvta.to.shared.u64 t, %1; cvt.u32.u64 %0, t; }" : "=r"(a) : "l"(p));
    return a;
}
static __device__ __forceinline__ uint64_t g2u(const void* p) {
    uint64_t a;
    asm("cvta.to.global.u64 %0, %1;" : "=l"(a) : "l"(p));
    return a;
}

// split fp32 pair into bf16x2 hi + bf16x2 lo (RN both stages); low half = first arg
static __device__ __forceinline__ void split2(float x0, float x1,
                                              uint32_t& hi2, uint32_t& lo2) {
    asm("cvt.rn.bf16x2.f32 %0, %1, %2;" : "=r"(hi2) : "f"(x1), "f"(x0));
    float h0 = __uint_as_float(hi2 << 16);
    float h1 = __uint_as_float(hi2 & 0xFFFF0000u);
    float l0 = x0 - h0, l1 = x1 - h1;
    asm("cvt.rn.bf16x2.f32 %0, %1, %2;" : "=r"(lo2) : "f"(l1), "f"(l0));
}

static __device__ __forceinline__ void mma_bf16(float* c, const uint32_t* a,
                                                uint32_t b0, uint32_t b1) {
    asm volatile(
        "mma.sync.aligned.m16n8k16.row.col.f32.bf16.bf16.f32 "
        "{%0,%1,%2,%3}, {%4,%5,%6,%7}, {%8,%9}, {%0,%1,%2,%3};"
        : "+f"(c[0]), "+f"(c[1]), "+f"(c[2]), "+f"(c[3])
        : "r"(a[0]), "r"(a[1]), "r"(a[2]), "r"(a[3]), "r"(b0), "r"(b1));
}

#define CPA16(dst, src) asm volatile("cp.async.cg.shared.global [%0], [%1], 16;" :: "r"(dst), "l"(src) : "memory")
#define CPA_COMMIT()    asm volatile("cp.async.commit_group;" ::: "memory")
#define LDS64F(vx, vy, a) asm volatile("ld.shared.v2.f32 {%0,%1},[%2];" : "=f"(vx), "=f"(vy) : "r"(a))
#define LDS128U(r0, r1, r2, r3, a) \
    asm volatile("ld.shared.v4.b32 {%0,%1,%2,%3},[%4];" \
                 : "=r"(r0), "=r"(r1), "=r"(r2), "=r"(r3) : "r"(a))

__global__ __launch_bounds__(TPB, 3)
void nkm_mma(const float* __restrict__ X, const float* __restrict__ C,
             float* __restrict__ out, int N) {
    extern __shared__ char smem[];
    const uint32_t sb = s2u(smem);
    float* sSqS = reinterpret_cast<float*>(smem + SSQ_REL);

    const int tid  = threadIdx.x;
    const int w    = tid >> 5;        // 0..7, warp owns rows 16w..16w+15
    const int lane = tid & 31;
    const int g    = lane >> 2;
    const int ql   = lane & 3;
    const int blockBase = blockIdx.x * MROWS;

    // ---- cp.async source/dest maps ----
    const uint64_t Xg = g2u(X);
    uint64_t xsrc[4];
    uint32_t xdst[4];
#pragma unroll
    for (int i = 0; i < 4; i++) {
        int idx = tid + 256 * i;
        int r = idx >> 3, f = idx & 7;
        int gr = blockBase + r;
        if (gr >= N) gr = N - 1;      // clamp; outputs guarded
        xsrc[i] = Xg + ((uint64_t)gr * DIM + 4 * (uint64_t)f) * 4ull;
        xdst[i] = (uint32_t)(PXB * r + 16 * f);
    }
    const uint64_t csrc = g2u(g_Cp) + (uint64_t)tid * 16ull;
    const uint32_t cdst = CP_REL + (uint32_t)tid * 16u;

#define ISSUE_X(ktv, stg)                                                       \
    do {                                                                        \
        uint32_t _bs = sb + (uint32_t)(stg) * STAGE_B;                          \
        uint64_t _ko = (uint64_t)(ktv) * (KCH * 4);                             \
        CPA16(_bs + xdst[0], xsrc[0] + _ko);                                    \
        CPA16(_bs + xdst[1], xsrc[1] + _ko);                                    \
        CPA16(_bs + xdst[2], xsrc[2] + _ko);                                    \
        CPA16(_bs + xdst[3], xsrc[3] + _ko);                                    \
        CPA_COMMIT();                                                           \
    } while (0)
#define ISSUE_C(ktv, stg)                                                       \
    do {                                                                        \
        uint32_t _bs = sb + (uint32_t)(stg) * STAGE_B;                          \
        CPA16(_bs + cdst, csrc + (uint64_t)(ktv) * CP_B);                       \
        CPA_COMMIT();                                                           \
    } while (0)
#define ISSUE(ktv, stg)                                                         \
    do {                                                                        \
        uint32_t _bs = sb + (uint32_t)(stg) * STAGE_B;                          \
        uint64_t _ko = (uint64_t)(ktv) * (KCH * 4);                             \
        CPA16(_bs + xdst[0], xsrc[0] + _ko);                                    \
        CPA16(_bs + xdst[1], xsrc[1] + _ko);                                    \
        CPA16(_bs + xdst[2], xsrc[2] + _ko);                                    \
        CPA16(_bs + xdst[3], xsrc[3] + _ko);                                    \
        CPA16(_bs + cdst, csrc + (uint64_t)(ktv) * CP_B);                       \
        CPA_COMMIT();                                                           \
    } while (0)

    // ---- start X streaming immediately (overlaps with C packing) ----
    ISSUE_X(0, 0);                    // group 0
    ISSUE_X(1, 1);                    // group 1

    // ---- producer: first NCH CTAs each pack one C chunk ----
    if (blockIdx.x < NCH) {
        const int kt = blockIdx.x;
        float* scr = reinterpret_cast<float*>(smem + 2 * STAGE_B + CP_REL); // stage2 C region, 4KB
        {
            const float4* C4g = reinterpret_cast<const float4*>(C);
            float4 v = C4g[(tid >> 3) * (DIM / 4) + kt * 8 + (tid & 7)];
            *reinterpret_cast<float4*>(scr + (tid >> 3) * 32 + (tid & 7) * 4) = v;
        }
        __syncthreads();
        {
            const int l = tid & 31, s5 = (tid >> 5) & 1, nt = tid >> 6;
            const int gg = l >> 2, qq = l & 3;
            const int row = 8 * nt + gg;
            const int k0 = 16 * s5 + 2 * qq;
            float a0 = scr[row * 32 + k0],     a1 = scr[row * 32 + k0 + 1];
            float b0 = scr[row * 32 + k0 + 8], b1 = scr[row * 32 + k0 + 9];
            uint32_t w0, w1, w2, w3;
            split2(a0, a1, w0, w2);
            split2(b0, b1, w1, w3);
            g_Cp[(kt * 8 + nt * 2 + s5) * 32 + l] = make_uint4(w0, w1, w2, w3);
            if (tid < KC) {
                float sq = 0.0f;
#pragma unroll
                for (int i = 0; i < 32; i++) { float c = scr[tid * 32 + i]; sq += c * c; }
                g_sqPart[kt * KC + tid] = sq;
            }
        }
        __syncthreads();
        if (tid == 0) { __threadfence(); atomicAdd(&g_ctr, 1u); }
    }

    // ---- consumer spin: wait until all NCH chunks are packed ----
    if (tid == 0) {
        unsigned int v;
        do {
            asm volatile("ld.global.acquire.gpu.u32 %0, [%1];" : "=r"(v) : "l"(&g_ctr));
        } while (v < (unsigned)NCH);
    }
    __syncthreads();

    // sSq = sum of per-chunk partials
    if (tid < KC) {
        float s = 0.0f;
#pragma unroll
        for (int kt = 0; kt < NCH; kt++) s += g_sqPart[kt * KC + tid];
        sSqS[tid] = s;
    }

    ISSUE_C(0, 0);                    // group 2
    ISSUE_C(1, 1);                    // group 3

    float acc[4][4];
#pragma unroll
    for (int nt = 0; nt < 4; nt++)
#pragma unroll
        for (int i = 0; i < 4; i++) acc[nt][i] = 0.0f;

    const uint32_t aRow = (uint32_t)(PXB * (16 * w + g));   // X row byte offset
    const uint32_t bIdx = (uint32_t)(lane * 16);            // packed C lane offset

    int rd = 0;                       // read stage = kt % 3
#pragma unroll 1
    for (int kt = 0; kt < NCH; kt++) {
        if (kt + 1 < NCH) {
            asm volatile("cp.async.wait_group 1;" ::: "memory");
        } else {
            asm volatile("cp.async.wait_group 0;" ::: "memory");
        }
        __syncthreads();              // stage kt visible; stage (kt-1)%3 freed

        if (kt + 2 < NCH) {
            int ib = rd + 2; if (ib >= NSTG) ib -= NSTG;
            ISSUE(kt + 2, ib);
        }

        const uint32_t bb = sb + (uint32_t)rd * STAGE_B;
#pragma unroll
        for (int s = 0; s < 2; s++) {
            // A fragments: fp32 LDS.64 + in-register split
            const uint32_t aa = bb + aRow + 8 * ql + 64 * s;
            float2 f0, f1, f2, f3;
            LDS64F(f0.x, f0.y, aa);                 // row g,   k 2ql..
            LDS64F(f1.x, f1.y, aa + 8 * PXB);       // row g+8
            LDS64F(f2.x, f2.y, aa + 32);            // row g,   k+8
            LDS64F(f3.x, f3.y, aa + 8 * PXB + 32);  // row g+8, k+8
            uint32_t ah[4], al[4];
            split2(f0.x, f0.y, ah[0], al[0]);
            split2(f1.x, f1.y, ah[1], al[1]);
            split2(f2.x, f2.y, ah[2], al[2]);
            split2(f3.x, f3.y, ah[3], al[3]);

#pragma unroll
            for (int nt = 0; nt < 4; nt++) {
                uint32_t bh0, bh1, bl0, bl1;
                LDS128U(bh0, bh1, bl0, bl1,
                        bb + CP_REL + (uint32_t)((nt * 2 + s) * 512) + bIdx);
                mma_bf16(acc[nt], ah, bh0, bh1);   // hi*hi
                mma_bf16(acc[nt], ah, bl0, bl1);   // hi*lo
                mma_bf16(acc[nt], al, bh0, bh1);   // lo*hi
            }
        }
        if (++rd == NSTG) rd = 0;
    }

    // ---- epilogue: s = 2*dot - sq ; top2 per row; merge across quad ----
    const float NEG_INF = -__int_as_float(0x7f800000);
    float m1[2] = {NEG_INF, NEG_INF};
    float m2[2] = {NEG_INF, NEG_INF};
#pragma unroll
    for (int nt = 0; nt < 4; nt++) {
        const int c0 = 8 * nt + ql * 2;
        const float q0 = sSqS[c0], q1 = sSqS[c0 + 1];
        float s;
        s = 2.0f * acc[nt][0] - q0;
        if (s > m1[0]) { m2[0] = m1[0]; m1[0] = s; } else if (s > m2[0]) m2[0] = s;
        s = 2.0f * acc[nt][1] - q1;
        if (s > m1[0]) { m2[0] = m1[0]; m1[0] = s; } else if (s > m2[0]) m2[0] = s;
        s = 2.0f * acc[nt][2] - q0;
        if (s > m1[1]) { m2[1] = m1[1]; m1[1] = s; } else if (s > m2[1]) m2[1] = s;
        s = 2.0f * acc[nt][3] - q1;
        if (s > m1[1]) { m2[1] = m1[1]; m1[1] = s; } else if (s > m2[1]) m2[1] = s;
    }
#pragma unroll
    for (int delta = 1; delta <= 2; delta <<= 1) {
#pragma unroll
        for (int r = 0; r < 2; r++) {
            float om1 = __shfl_xor_sync(0xffffffffu, m1[r], delta);
            float om2 = __shfl_xor_sync(0xffffffffu, m2[r], delta);
            float nm1 = fmaxf(m1[r], om1);
            float nm2 = fmaxf(fminf(m1[r], om1), fmaxf(m2[r], om2));
            m1[r] = nm1;
            m2[r] = nm2;
        }
    }
    if (ql == 0) {
        int r0 = blockBase + 16 * w + g;
        if (r0 < N)     out[r0]     = m1[0] - m2[0];
        if (r0 + 8 < N) out[r0 + 8] = m1[1] - m2[1];
    }
#undef ISSUE
#undef ISSUE_X
#undef ISSUE_C
}

extern "C" void kernel_launch(void* const* d_in, const int* in_sizes, int n_in,
                              void* d_out, int out_size) {
    const float* X = (const float*)d_in[0];   // [N, 1024]
    const float* C = (const float*)d_in[1];   // [32, 1024]
    float* out = (float*)d_out;               // [N]
    int N = in_sizes[0] / DIM;
    int nb = (N + MROWS - 1) / MROWS;

    cudaFuncSetAttribute(nkm_mma, cudaFuncAttributeMaxDynamicSharedMemorySize, SMEM_B);
    nkm_mma<<<nb, TPB, SMEM_B>>>(X, C, out, N);
}